// round 14
// baseline (speedup 1.0000x reference)
#include <cuda_runtime.h>

// AttentionStem: per-pixel 4x4 local window attention. B=4, IC=3, OC=64, H=W=128.
// R14: eliminate the 48-reg window state: pre-paired x in shared
//      (spx[c][r][k] = (x[k],x[k+1])) so each window pair is one LDS.64 at an
//      immediate offset. Regs ~80 -> ~60 => 4 CTAs/SM (32 warps) for stall
//      coverage. fma work unchanged; +24 LDS/channel (LDS pipe far from limit).
//      prep unchanged from R13.

typedef unsigned long long u64;

#define LOG2E 1.4426950408889634f

__device__ __forceinline__ u64 pk2(float lo, float hi) {
    u64 r; asm("mov.b64 %0,{%1,%2};" : "=l"(r) : "f"(lo), "f"(hi)); return r;
}
__device__ __forceinline__ void upk2(u64 a, float& lo, float& hi) {
    asm("mov.b64 {%0,%1},%2;" : "=f"(lo), "=f"(hi) : "l"(a));
}
__device__ __forceinline__ u64 fma2_(u64 a, u64 b, u64 c) {
    u64 r; asm("fma.rn.f32x2 %0,%1,%2,%3;" : "=l"(r) : "l"(a), "l"(b), "l"(c)); return r;
}
__device__ __forceinline__ u64 mul2_(u64 a, u64 b) {
    u64 r; asm("mul.rn.f32x2 %0,%1,%2;" : "=l"(r) : "l"(a), "l"(b)); return r;
}
__device__ __forceinline__ u64 add2_(u64 a, u64 b) {
    u64 r; asm("add.rn.f32x2 %0,%1,%2;" : "=l"(r) : "l"(a), "l"(b)); return r;
}
__device__ __forceinline__ float ex2_(float x) {
    float r; asm("ex2.approx.f32 %0,%1;" : "=f"(r) : "f"(x)); return r;
}

// Precomputed: mixed value weights (u64-packed pairs) and folded q/k weights.
__device__ u64    g_wv[64 * 24];   // [o][c][p], float view [o*48 + c*16 + ij]
__device__ float4 g_kw[64];
__device__ float4 g_qw[64];        // pre-scaled by LOG2E

__global__ __launch_bounds__(256)
void prep_kernel(const float* __restrict__ key_w,
                 const float* __restrict__ query_w,
                 const float* __restrict__ value_w,
                 const float* __restrict__ emb_a,
                 const float* __restrict__ emb_b,
                 const float* __restrict__ emb_mix) {
    __shared__ float sh_vw[768];
    __shared__ float sh_mix[256];
    __shared__ float sh_ab[512];
    __shared__ float sh_lab[32];
    __shared__ float sh_emb[4][16];
    int t = threadIdx.x;

    if (t < 192) {
        ((float4*)sh_vw)[t] = ((const float4*)value_w)[t];
    } else {
        ((float4*)sh_mix)[t - 192] = ((const float4*)emb_mix)[t - 192];
    }
    if (t < 64) {
        ((float4*)sh_ab)[t] = ((const float4*)emb_a)[t];
    } else if (t < 128) {
        ((float4*)sh_ab)[t] = ((const float4*)emb_b)[t - 64];
    } else if (t < 192) {
        int o = t - 128;
        g_kw[o] = make_float4(key_w[o * 3], key_w[o * 3 + 1], key_w[o * 3 + 2], 0.f);
        g_qw[o] = make_float4(query_w[o * 3] * LOG2E,
                              query_w[o * 3 + 1] * LOG2E,
                              query_w[o * 3 + 2] * LOG2E, 0.f);
    }
    __syncthreads();

    {
        int d = t >> 3;
        int part = t & 7;
        int m = d & 3, i4 = (d >> 2) & 3, ab = d >> 4;
        const float* e = sh_ab + ab * 256;
        float s = 0.f;
#pragma unroll
        for (int k = 0; k < 8; k++) {
            int o = part * 8 + k;
            s += sh_mix[m * 64 + o] * e[o * 4 + i4];
        }
        s += __shfl_xor_sync(0xffffffffu, s, 1);
        s += __shfl_xor_sync(0xffffffffu, s, 2);
        s += __shfl_xor_sync(0xffffffffu, s, 4);
        if (part == 0) sh_lab[d] = s;
    }
    __syncthreads();

    if (t < 16) {
        int i = t >> 2, j = t & 3;
        float lg[4];
#pragma unroll
        for (int m = 0; m < 4; m++)
            lg[m] = sh_lab[(i << 2) + m] + sh_lab[16 + (j << 2) + m];
        float mx = fmaxf(fmaxf(lg[0], lg[1]), fmaxf(lg[2], lg[3]));
        float e[4], s = 0.f;
#pragma unroll
        for (int m = 0; m < 4; m++) { e[m] = __expf(lg[m] - mx); s += e[m]; }
        float inv = __fdividef(1.f, s);
#pragma unroll
        for (int m = 0; m < 4; m++) sh_emb[m][t] = e[m] * inv;
    }
    __syncthreads();

    float* wvf = (float*)g_wv;
#pragma unroll
    for (int k = 0; k < 12; k++) {
        int f = t + k * 256;
        int o = f / 48, r = f % 48, c = r >> 4, ij = r & 15;
        float acc = 0.f;
#pragma unroll
        for (int m = 0; m < 4; m++)
            acc += sh_emb[m][ij] * sh_vw[(m * 64 + o) * 3 + c];
        wvf[f] = acc;
    }
}

__global__ __launch_bounds__(256, 4)
void attn_kernel(const float* __restrict__ x, float* __restrict__ out) {
    __shared__ float  sx[3 * 5 * 132];   // [c][tile row][padded col]
    __shared__ u64    spx[3 * 5 * 132];  // paired: (x[k], x[k+1])
    __shared__ float4 sh_kw[16];
    __shared__ float4 sh_qw[16];
    __shared__ u64    sh_wv[16 * 24];    // [o][c][p]

    int tid = threadIdx.x;
    int oq = blockIdx.x & 3;             // quarter of the 64 channels
    int rest = blockIdx.x >> 2;
    int b = rest >> 6;
    int h0 = (rest & 63) * 2;            // output rows h0, h0+1

    // Prologue pass 1: x tile + wv + kw/qw.
    for (int idx = tid; idx < 1980; idx += 256) {
        int c = idx / 660, rem = idx % 660, r = rem / 132, cc = rem % 132;
        int hr = h0 - 2 + r, wc = cc - 2;
        float v = 0.f;
        if (hr >= 0 && hr < 128 && wc >= 0 && wc < 128)
            v = x[((b * 3 + c) * 128 + hr) * 128 + wc];
        sx[idx] = v;
    }
    if (tid < 192) {
        const ulonglong2* src = (const ulonglong2*)(g_wv + oq * 384);
        ((ulonglong2*)sh_wv)[tid] = src[tid];
    }
    if (tid >= 192 && tid < 208) {
        sh_kw[tid - 192] = g_kw[oq * 16 + (tid - 192)];
        sh_qw[tid - 192] = g_qw[oq * 16 + (tid - 192)];
    }
    __syncthreads();

    // Prologue pass 2: build the paired array (k = 0..130 per (c,row)).
    for (int idx = tid; idx < 1965; idx += 256) {
        int cr = idx / 131, k = idx % 131;     // cr = c*5 + r
        int base = cr * 132 + k;
        spx[base] = pk2(sx[base], sx[base + 1]);
    }
    __syncthreads();

    // This thread's pixel: row group r0 (0/1), column w.
    int r0 = tid >> 7;
    int w = tid & 127;

    // Center pixel values (row r0+2, col w+2) for q.
    float c0 = sx[0 * 660 + (r0 + 2) * 132 + w + 2];
    float c1 = sx[1 * 660 + (r0 + 2) * 132 + w + 2];
    float c2 = sx[2 * 660 + (r0 + 2) * 132 + w + 2];

    // Base pointer for this thread's window pairs.
    const u64* pxb = spx + r0 * 132 + w;

    float* outp = out + (((b * 64) + oq * 16) * 128 + (h0 + r0)) * 128 + w;

#pragma unroll 2
    for (int o = 0; o < 16; o++) {
        float4 qw = sh_qw[o];
        float q = qw.x * c0 + qw.y * c1 + qw.z * c2;
        float4 kw = sh_kw[o];
        float qk0 = q * kw.x, qk1 = q * kw.y, qk2 = q * kw.z;
        u64 k0 = pk2(qk0, qk0), k1 = pk2(qk1, qk1), k2 = pk2(qk2, qk2);
        const u64* wvp = sh_wv + o * 24;

        u64 acc = 0ull, ss = 0ull;
#pragma unroll
        for (int pp = 0; pp < 4; pp++) {
            ulonglong2 wv0 = *(const ulonglong2*)(wvp + 2 * pp);
            ulonglong2 wv1 = *(const ulonglong2*)(wvp + 8 + 2 * pp);
            ulonglong2 wv2 = *(const ulonglong2*)(wvp + 16 + 2 * pp);
#pragma unroll
            for (int s = 0; s < 2; s++) {
                int p = 2 * pp + s;
                int off = (p >> 1) * 132 + (p & 1) * 2;   // compile-time
                u64 x0 = pxb[off];
                u64 x1 = pxb[660 + off];
                u64 x2 = pxb[1320 + off];
                u64 l2 = fma2_(k0, x0, fma2_(k1, x1, mul2_(k2, x2)));
                float l0, l1; upk2(l2, l0, l1);
                u64 e2 = pk2(ex2_(l0), ex2_(l1));
                u64 wva = s ? wv0.y : wv0.x;
                u64 wvb = s ? wv1.y : wv1.x;
                u64 wvc = s ? wv2.y : wv2.x;
                u64 v2 = fma2_(wva, x0, fma2_(wvb, x1, mul2_(wvc, x2)));
                acc = fma2_(e2, v2, acc);
                ss  = add2_(e2, ss);
            }
        }
        float a0, a1, s0, s1;
        upk2(acc, a0, a1);
        upk2(ss, s0, s1);
        outp[o * 16384] = __fdividef(a0 + a1, s0 + s1);
    }
}

extern "C" void kernel_launch(void* const* d_in, const int* in_sizes, int n_in,
                              void* d_out, int out_size) {
    const float* x       = (const float*)d_in[0];
    const float* key_w   = (const float*)d_in[1];
    const float* query_w = (const float*)d_in[2];
    const float* value_w = (const float*)d_in[3];
    const float* emb_a   = (const float*)d_in[4];
    const float* emb_b   = (const float*)d_in[5];
    const float* emb_mix = (const float*)d_in[6];
    float* out = (float*)d_out;

    prep_kernel<<<1, 256>>>(key_w, query_w, value_w, emb_a, emb_b, emb_mix);
    attn_kernel<<<1024, 256>>>(x, out);
}

// round 15
// speedup vs baseline: 1.1485x; 1.1485x over previous
#include <cuda_runtime.h>

// AttentionStem: per-pixel 4x4 local window attention. B=4, IC=3, OC=64, H=W=128.
// R15: R13 base (best: 39.3us) + two bounded changes:
//  (a) PDL: attn launched with programmatic stream serialization; x-tile loads
//      run concurrently with prep, cudaGridDependencySynchronize() before
//      reading prep outputs (hides the ~2us prep+gap).
//  (b) channel loop unroll 2 -> 4 for more scheduler-visible ILP
//      (launch_bounds(256,3) caps regs at 85; R13 used 80).

typedef unsigned long long u64;

#define LOG2E 1.4426950408889634f

__device__ __forceinline__ u64 pk2(float lo, float hi) {
    u64 r; asm("mov.b64 %0,{%1,%2};" : "=l"(r) : "f"(lo), "f"(hi)); return r;
}
__device__ __forceinline__ void upk2(u64 a, float& lo, float& hi) {
    asm("mov.b64 {%0,%1},%2;" : "=f"(lo), "=f"(hi) : "l"(a));
}
__device__ __forceinline__ u64 fma2_(u64 a, u64 b, u64 c) {
    u64 r; asm("fma.rn.f32x2 %0,%1,%2,%3;" : "=l"(r) : "l"(a), "l"(b), "l"(c)); return r;
}
__device__ __forceinline__ u64 mul2_(u64 a, u64 b) {
    u64 r; asm("mul.rn.f32x2 %0,%1,%2;" : "=l"(r) : "l"(a), "l"(b)); return r;
}
__device__ __forceinline__ u64 add2_(u64 a, u64 b) {
    u64 r; asm("add.rn.f32x2 %0,%1,%2;" : "=l"(r) : "l"(a), "l"(b)); return r;
}
__device__ __forceinline__ float ex2_(float x) {
    float r; asm("ex2.approx.f32 %0,%1;" : "=f"(r) : "f"(x)); return r;
}
__device__ __forceinline__ float lo32(u64 a) {
    return __int_as_float((int)(unsigned)a);
}

// Precomputed: mixed value weights (u64-packed pairs) and folded q/k weights.
__device__ u64    g_wv[64 * 24];   // [o][c][p], float view [o*48 + c*16 + ij]
__device__ float4 g_kw[64];
__device__ float4 g_qw[64];        // pre-scaled by LOG2E

__global__ __launch_bounds__(256)
void prep_kernel(const float* __restrict__ key_w,
                 const float* __restrict__ query_w,
                 const float* __restrict__ value_w,
                 const float* __restrict__ emb_a,
                 const float* __restrict__ emb_b,
                 const float* __restrict__ emb_mix) {
    __shared__ float sh_vw[768];
    __shared__ float sh_mix[256];
    __shared__ float sh_ab[512];
    __shared__ float sh_lab[32];
    __shared__ float sh_emb[4][16];
    int t = threadIdx.x;

    if (t < 192) {
        ((float4*)sh_vw)[t] = ((const float4*)value_w)[t];
    } else {
        ((float4*)sh_mix)[t - 192] = ((const float4*)emb_mix)[t - 192];
    }
    if (t < 64) {
        ((float4*)sh_ab)[t] = ((const float4*)emb_a)[t];
    } else if (t < 128) {
        ((float4*)sh_ab)[t] = ((const float4*)emb_b)[t - 64];
    } else if (t < 192) {
        int o = t - 128;
        g_kw[o] = make_float4(key_w[o * 3], key_w[o * 3 + 1], key_w[o * 3 + 2], 0.f);
        g_qw[o] = make_float4(query_w[o * 3] * LOG2E,
                              query_w[o * 3 + 1] * LOG2E,
                              query_w[o * 3 + 2] * LOG2E, 0.f);
    }
    __syncthreads();

    {
        int d = t >> 3;
        int part = t & 7;
        int m = d & 3, i4 = (d >> 2) & 3, ab = d >> 4;
        const float* e = sh_ab + ab * 256;
        float s = 0.f;
#pragma unroll
        for (int k = 0; k < 8; k++) {
            int o = part * 8 + k;
            s += sh_mix[m * 64 + o] * e[o * 4 + i4];
        }
        s += __shfl_xor_sync(0xffffffffu, s, 1);
        s += __shfl_xor_sync(0xffffffffu, s, 2);
        s += __shfl_xor_sync(0xffffffffu, s, 4);
        if (part == 0) sh_lab[d] = s;
    }
    __syncthreads();

    if (t < 16) {
        int i = t >> 2, j = t & 3;
        float lg[4];
#pragma unroll
        for (int m = 0; m < 4; m++)
            lg[m] = sh_lab[(i << 2) + m] + sh_lab[16 + (j << 2) + m];
        float mx = fmaxf(fmaxf(lg[0], lg[1]), fmaxf(lg[2], lg[3]));
        float e[4], s = 0.f;
#pragma unroll
        for (int m = 0; m < 4; m++) { e[m] = __expf(lg[m] - mx); s += e[m]; }
        float inv = __fdividef(1.f, s);
#pragma unroll
        for (int m = 0; m < 4; m++) sh_emb[m][t] = e[m] * inv;
    }
    __syncthreads();

    float* wvf = (float*)g_wv;
#pragma unroll
    for (int k = 0; k < 12; k++) {
        int f = t + k * 256;
        int o = f / 48, r = f % 48, c = r >> 4, ij = r & 15;
        float acc = 0.f;
#pragma unroll
        for (int m = 0; m < 4; m++)
            acc += sh_emb[m][ij] * sh_vw[(m * 64 + o) * 3 + c];
        wvf[f] = acc;
    }
}

__global__ __launch_bounds__(256, 3)
void attn_kernel(const float* __restrict__ x, float* __restrict__ out) {
    __shared__ float  sh_x[3][5][132];   // [c][tile row][padded col]
    __shared__ float4 sh_kw[16];
    __shared__ float4 sh_qw[16];
    __shared__ u64    sh_wv[16 * 24];    // [o][c][p]

    int tid = threadIdx.x;
    int oq = blockIdx.x & 3;             // quarter of the 64 channels
    int rest = blockIdx.x >> 2;
    int b = rest >> 6;
    int h0 = (rest & 63) * 2;            // output rows h0, h0+1

    // Phase 1 (independent of prep): x tile loads.
    for (int idx = tid; idx < 3 * 5 * 132; idx += 256) {
        int c = idx / 660, rem = idx % 660, r = rem / 132, cc = rem % 132;
        int hr = h0 - 2 + r, wc = cc - 2;
        float v = 0.f;
        if (hr >= 0 && hr < 128 && wc >= 0 && wc < 128)
            v = x[((b * 3 + c) * 128 + hr) * 128 + wc];
        sh_x[c][r][cc] = v;
    }

    // Wait for prep_kernel's g_wv / g_kw / g_qw writes (PDL).
    cudaGridDependencySynchronize();

    // Phase 2: prep outputs.
    if (tid < 192) {
        const ulonglong2* src = (const ulonglong2*)(g_wv + oq * 384);
        ((ulonglong2*)sh_wv)[tid] = src[tid];
    }
    if (tid >= 192 && tid < 208) {
        sh_kw[tid - 192] = g_kw[oq * 16 + (tid - 192)];
        sh_qw[tid - 192] = g_qw[oq * 16 + (tid - 192)];
    }
    __syncthreads();

    // This thread's pixel: row group r0 (0/1), column w.
    int r0 = tid >> 7;
    int w = tid & 127;

    // Window into registers, packed by (same i, adjacent j) pairs.
    u64 wp0[8], wp1[8], wp2[8];
#pragma unroll
    for (int p = 0; p < 8; p++) {
        int i = (p >> 1) + r0, j0 = (p & 1) * 2;
        wp0[p] = pk2(sh_x[0][i][w + j0], sh_x[0][i][w + j0 + 1]);
        wp1[p] = pk2(sh_x[1][i][w + j0], sh_x[1][i][w + j0 + 1]);
        wp2[p] = pk2(sh_x[2][i][w + j0], sh_x[2][i][w + j0 + 1]);
    }

    float* outp = out + (((b * 64) + oq * 16) * 128 + (h0 + r0)) * 128 + w;

#pragma unroll 4
    for (int o = 0; o < 16; o++) {
        float4 qw = sh_qw[o];
        // center pixel = low half of pair 5 (i=2, j=2)
        float q = qw.x * lo32(wp0[5]) + qw.y * lo32(wp1[5]) + qw.z * lo32(wp2[5]);
        float4 kw = sh_kw[o];
        float qk0 = q * kw.x, qk1 = q * kw.y, qk2 = q * kw.z;
        u64 k0 = pk2(qk0, qk0), k1 = pk2(qk1, qk1), k2 = pk2(qk2, qk2);
        const u64* wvp = sh_wv + o * 24;

        u64 acc = 0ull, ss = 0ull;
#pragma unroll
        for (int pp = 0; pp < 4; pp++) {
            ulonglong2 wv0 = *(const ulonglong2*)(wvp + 2 * pp);
            ulonglong2 wv1 = *(const ulonglong2*)(wvp + 8 + 2 * pp);
            ulonglong2 wv2 = *(const ulonglong2*)(wvp + 16 + 2 * pp);
            {
                int p = 2 * pp;
                u64 l2 = fma2_(k0, wp0[p], fma2_(k1, wp1[p], mul2_(k2, wp2[p])));
                float l0, l1; upk2(l2, l0, l1);
                u64 e2 = pk2(ex2_(l0), ex2_(l1));
                u64 v2 = fma2_(wv0.x, wp0[p], fma2_(wv1.x, wp1[p], mul2_(wv2.x, wp2[p])));
                acc = fma2_(e2, v2, acc);
                ss  = add2_(e2, ss);
            }
            {
                int p = 2 * pp + 1;
                u64 l2 = fma2_(k0, wp0[p], fma2_(k1, wp1[p], mul2_(k2, wp2[p])));
                float l0, l1; upk2(l2, l0, l1);
                u64 e2 = pk2(ex2_(l0), ex2_(l1));
                u64 v2 = fma2_(wv0.y, wp0[p], fma2_(wv1.y, wp1[p], mul2_(wv2.y, wp2[p])));
                acc = fma2_(e2, v2, acc);
                ss  = add2_(e2, ss);
            }
        }
        float a0, a1, s0, s1;
        upk2(acc, a0, a1);
        upk2(ss, s0, s1);
        outp[o * 16384] = __fdividef(a0 + a1, s0 + s1);
    }
}

extern "C" void kernel_launch(void* const* d_in, const int* in_sizes, int n_in,
                              void* d_out, int out_size) {
    const float* x       = (const float*)d_in[0];
    const float* key_w   = (const float*)d_in[1];
    const float* query_w = (const float*)d_in[2];
    const float* value_w = (const float*)d_in[3];
    const float* emb_a   = (const float*)d_in[4];
    const float* emb_b   = (const float*)d_in[5];
    const float* emb_mix = (const float*)d_in[6];
    float* out = (float*)d_out;

    prep_kernel<<<1, 256>>>(key_w, query_w, value_w, emb_a, emb_b, emb_mix);

    // attn with programmatic dependent launch: starts while prep runs;
    // device code syncs via cudaGridDependencySynchronize() before reading
    // prep outputs.
    cudaLaunchConfig_t cfg = {};
    cfg.gridDim = dim3(1024, 1, 1);
    cfg.blockDim = dim3(256, 1, 1);
    cfg.dynamicSmemBytes = 0;
    cfg.stream = 0;
    cudaLaunchAttribute attrs[1];
    attrs[0].id = cudaLaunchAttributeProgrammaticStreamSerialization;
    attrs[0].val.programmaticStreamSerializationAllowed = 1;
    cfg.attrs = attrs;
    cfg.numAttrs = 1;
    cudaLaunchKernelEx(&cfg, attn_kernel, x, (float*)d_out);
}

// round 17
// speedup vs baseline: 1.1664x; 1.0156x over previous
#include <cuda_runtime.h>

// AttentionStem: per-pixel 4x4 local window attention. B=4, IC=3, OC=64, H=W=128.
// R17 (= R16 resubmit after infra failure): recombination of measured-best
// components:
//  - attn mainloop = R13 exactly (unroll 2; attn 36.0us measured; R15's
//    unroll-4 variant was 38.4us -> reverted),
//  - PDL launch from R15 (prep hidden behind attn's x-tile loads; gap 1.2us).

typedef unsigned long long u64;

#define LOG2E 1.4426950408889634f

__device__ __forceinline__ u64 pk2(float lo, float hi) {
    u64 r; asm("mov.b64 %0,{%1,%2};" : "=l"(r) : "f"(lo), "f"(hi)); return r;
}
__device__ __forceinline__ void upk2(u64 a, float& lo, float& hi) {
    asm("mov.b64 {%0,%1},%2;" : "=f"(lo), "=f"(hi) : "l"(a));
}
__device__ __forceinline__ u64 fma2_(u64 a, u64 b, u64 c) {
    u64 r; asm("fma.rn.f32x2 %0,%1,%2,%3;" : "=l"(r) : "l"(a), "l"(b), "l"(c)); return r;
}
__device__ __forceinline__ u64 mul2_(u64 a, u64 b) {
    u64 r; asm("mul.rn.f32x2 %0,%1,%2;" : "=l"(r) : "l"(a), "l"(b)); return r;
}
__device__ __forceinline__ u64 add2_(u64 a, u64 b) {
    u64 r; asm("add.rn.f32x2 %0,%1,%2;" : "=l"(r) : "l"(a), "l"(b)); return r;
}
__device__ __forceinline__ float ex2_(float x) {
    float r; asm("ex2.approx.f32 %0,%1;" : "=f"(r) : "f"(x)); return r;
}
__device__ __forceinline__ float lo32(u64 a) {
    return __int_as_float((int)(unsigned)a);
}

// Precomputed: mixed value weights (u64-packed pairs) and folded q/k weights.
__device__ u64    g_wv[64 * 24];   // [o][c][p], float view [o*48 + c*16 + ij]
__device__ float4 g_kw[64];
__device__ float4 g_qw[64];        // pre-scaled by LOG2E

__global__ __launch_bounds__(256)
void prep_kernel(const float* __restrict__ key_w,
                 const float* __restrict__ query_w,
                 const float* __restrict__ value_w,
                 const float* __restrict__ emb_a,
                 const float* __restrict__ emb_b,
                 const float* __restrict__ emb_mix) {
    __shared__ float sh_vw[768];
    __shared__ float sh_mix[256];
    __shared__ float sh_ab[512];
    __shared__ float sh_lab[32];
    __shared__ float sh_emb[4][16];
    int t = threadIdx.x;

    if (t < 192) {
        ((float4*)sh_vw)[t] = ((const float4*)value_w)[t];
    } else {
        ((float4*)sh_mix)[t - 192] = ((const float4*)emb_mix)[t - 192];
    }
    if (t < 64) {
        ((float4*)sh_ab)[t] = ((const float4*)emb_a)[t];
    } else if (t < 128) {
        ((float4*)sh_ab)[t] = ((const float4*)emb_b)[t - 64];
    } else if (t < 192) {
        int o = t - 128;
        g_kw[o] = make_float4(key_w[o * 3], key_w[o * 3 + 1], key_w[o * 3 + 2], 0.f);
        g_qw[o] = make_float4(query_w[o * 3] * LOG2E,
                              query_w[o * 3 + 1] * LOG2E,
                              query_w[o * 3 + 2] * LOG2E, 0.f);
    }
    __syncthreads();

    {
        int d = t >> 3;
        int part = t & 7;
        int m = d & 3, i4 = (d >> 2) & 3, ab = d >> 4;
        const float* e = sh_ab + ab * 256;
        float s = 0.f;
#pragma unroll
        for (int k = 0; k < 8; k++) {
            int o = part * 8 + k;
            s += sh_mix[m * 64 + o] * e[o * 4 + i4];
        }
        s += __shfl_xor_sync(0xffffffffu, s, 1);
        s += __shfl_xor_sync(0xffffffffu, s, 2);
        s += __shfl_xor_sync(0xffffffffu, s, 4);
        if (part == 0) sh_lab[d] = s;
    }
    __syncthreads();

    if (t < 16) {
        int i = t >> 2, j = t & 3;
        float lg[4];
#pragma unroll
        for (int m = 0; m < 4; m++)
            lg[m] = sh_lab[(i << 2) + m] + sh_lab[16 + (j << 2) + m];
        float mx = fmaxf(fmaxf(lg[0], lg[1]), fmaxf(lg[2], lg[3]));
        float e[4], s = 0.f;
#pragma unroll
        for (int m = 0; m < 4; m++) { e[m] = __expf(lg[m] - mx); s += e[m]; }
        float inv = __fdividef(1.f, s);
#pragma unroll
        for (int m = 0; m < 4; m++) sh_emb[m][t] = e[m] * inv;
    }
    __syncthreads();

    float* wvf = (float*)g_wv;
#pragma unroll
    for (int k = 0; k < 12; k++) {
        int f = t + k * 256;
        int o = f / 48, r = f % 48, c = r >> 4, ij = r & 15;
        float acc = 0.f;
#pragma unroll
        for (int m = 0; m < 4; m++)
            acc += sh_emb[m][ij] * sh_vw[(m * 64 + o) * 3 + c];
        wvf[f] = acc;
    }
}

__global__ __launch_bounds__(256, 3)
void attn_kernel(const float* __restrict__ x, float* __restrict__ out) {
    __shared__ float  sh_x[3][5][132];   // [c][tile row][padded col]
    __shared__ float4 sh_kw[16];
    __shared__ float4 sh_qw[16];
    __shared__ u64    sh_wv[16 * 24];    // [o][c][p]

    int tid = threadIdx.x;
    int oq = blockIdx.x & 3;             // quarter of the 64 channels
    int rest = blockIdx.x >> 2;
    int b = rest >> 6;
    int h0 = (rest & 63) * 2;            // output rows h0, h0+1

    // Phase 1 (independent of prep): x tile loads.
    for (int idx = tid; idx < 3 * 5 * 132; idx += 256) {
        int c = idx / 660, rem = idx % 660, r = rem / 132, cc = rem % 132;
        int hr = h0 - 2 + r, wc = cc - 2;
        float v = 0.f;
        if (hr >= 0 && hr < 128 && wc >= 0 && wc < 128)
            v = x[((b * 3 + c) * 128 + hr) * 128 + wc];
        sh_x[c][r][cc] = v;
    }

    // Wait for prep_kernel's g_wv / g_kw / g_qw writes (PDL).
    cudaGridDependencySynchronize();

    // Phase 2: prep outputs.
    if (tid < 192) {
        const ulonglong2* src = (const ulonglong2*)(g_wv + oq * 384);
        ((ulonglong2*)sh_wv)[tid] = src[tid];
    }
    if (tid >= 192 && tid < 208) {
        sh_kw[tid - 192] = g_kw[oq * 16 + (tid - 192)];
        sh_qw[tid - 192] = g_qw[oq * 16 + (tid - 192)];
    }
    __syncthreads();

    // This thread's pixel: row group r0 (0/1), column w.
    int r0 = tid >> 7;
    int w = tid & 127;

    // Window into registers, packed by (same i, adjacent j) pairs.
    u64 wp0[8], wp1[8], wp2[8];
#pragma unroll
    for (int p = 0; p < 8; p++) {
        int i = (p >> 1) + r0, j0 = (p & 1) * 2;
        wp0[p] = pk2(sh_x[0][i][w + j0], sh_x[0][i][w + j0 + 1]);
        wp1[p] = pk2(sh_x[1][i][w + j0], sh_x[1][i][w + j0 + 1]);
        wp2[p] = pk2(sh_x[2][i][w + j0], sh_x[2][i][w + j0 + 1]);
    }

    float* outp = out + (((b * 64) + oq * 16) * 128 + (h0 + r0)) * 128 + w;

#pragma unroll 2
    for (int o = 0; o < 16; o++) {
        float4 qw = sh_qw[o];
        // center pixel = low half of pair 5 (i=2, j=2)
        float q = qw.x * lo32(wp0[5]) + qw.y * lo32(wp1[5]) + qw.z * lo32(wp2[5]);
        float4 kw = sh_kw[o];
        float qk0 = q * kw.x, qk1 = q * kw.y, qk2 = q * kw.z;
        u64 k0 = pk2(qk0, qk0), k1 = pk2(qk1, qk1), k2 = pk2(qk2, qk2);
        const u64* wvp = sh_wv + o * 24;

        u64 acc = 0ull, ss = 0ull;
#pragma unroll
        for (int pp = 0; pp < 4; pp++) {
            ulonglong2 wv0 = *(const ulonglong2*)(wvp + 2 * pp);
            ulonglong2 wv1 = *(const ulonglong2*)(wvp + 8 + 2 * pp);
            ulonglong2 wv2 = *(const ulonglong2*)(wvp + 16 + 2 * pp);
            {
                int p = 2 * pp;
                u64 l2 = fma2_(k0, wp0[p], fma2_(k1, wp1[p], mul2_(k2, wp2[p])));
                float l0, l1; upk2(l2, l0, l1);
                u64 e2 = pk2(ex2_(l0), ex2_(l1));
                u64 v2 = fma2_(wv0.x, wp0[p], fma2_(wv1.x, wp1[p], mul2_(wv2.x, wp2[p])));
                acc = fma2_(e2, v2, acc);
                ss  = add2_(e2, ss);
            }
            {
                int p = 2 * pp + 1;
                u64 l2 = fma2_(k0, wp0[p], fma2_(k1, wp1[p], mul2_(k2, wp2[p])));
                float l0, l1; upk2(l2, l0, l1);
                u64 e2 = pk2(ex2_(l0), ex2_(l1));
                u64 v2 = fma2_(wv0.y, wp0[p], fma2_(wv1.y, wp1[p], mul2_(wv2.y, wp2[p])));
                acc = fma2_(e2, v2, acc);
                ss  = add2_(e2, ss);
            }
        }
        float a0, a1, s0, s1;
        upk2(acc, a0, a1);
        upk2(ss, s0, s1);
        outp[o * 16384] = __fdividef(a0 + a1, s0 + s1);
    }
}

extern "C" void kernel_launch(void* const* d_in, const int* in_sizes, int n_in,
                              void* d_out, int out_size) {
    const float* x       = (const float*)d_in[0];
    const float* key_w   = (const float*)d_in[1];
    const float* query_w = (const float*)d_in[2];
    const float* value_w = (const float*)d_in[3];
    const float* emb_a   = (const float*)d_in[4];
    const float* emb_b   = (const float*)d_in[5];
    const float* emb_mix = (const float*)d_in[6];
    float* out = (float*)d_out;

    prep_kernel<<<1, 256>>>(key_w, query_w, value_w, emb_a, emb_b, emb_mix);

    // attn with programmatic dependent launch: starts while prep runs;
    // device code syncs via cudaGridDependencySynchronize() before reading
    // prep outputs.
    cudaLaunchConfig_t cfg = {};
    cfg.gridDim = dim3(1024, 1, 1);
    cfg.blockDim = dim3(256, 1, 1);
    cfg.dynamicSmemBytes = 0;
    cfg.stream = 0;
    cudaLaunchAttribute attrs[1];
    attrs[0].id = cudaLaunchAttributeProgrammaticStreamSerialization;
    attrs[0].val.programmaticStreamSerializationAllowed = 1;
    cfg.attrs = attrs;
    cfg.numAttrs = 1;
    cudaLaunchKernelEx(&cfg, attn_kernel, x, (float*)d_out);
}